// round 1
// baseline (speedup 1.0000x reference)
#include <cuda_runtime.h>

// Problem constants (fixed by setup_inputs)
#define BB 16
#define HH 2048
#define WW 2048
#define SS 5000
#define TOTAL (BB * SS)          // 80000 stations
#define THREADS 256
#define NBLK ((TOTAL + THREADS - 1) / THREADS)   // 313

__device__ float g_partials[NBLK];

__global__ void __launch_bounds__(THREADS)
station_loss_kernel(const float* __restrict__ pred,
                    const int*   __restrict__ pos,
                    const float* __restrict__ runoff)
{
    int idx = blockIdx.x * THREADS + threadIdx.x;
    float err2 = 0.0f;

    if (idx < TOTAL) {
        int b  = idx / SS;
        // station_positions[b, s, 0] = px (width/x), [b, s, 1] = py (height/y)
        int2 p = __ldg(reinterpret_cast<const int2*>(pos) + idx);
        int px = p.x;
        int py = p.y;

        const float* base = pred + (size_t)b * (size_t)(HH * WW);

        float sum = 0.0f;
        float cnt = 0.0f;
        #pragma unroll
        for (int dy = -1; dy <= 1; ++dy) {
            int y   = py + dy;
            bool vy = (y >= 0) & (y < HH);
            int yc  = min(max(y, 0), HH - 1);
            const float* row = base + (size_t)yc * WW;
            #pragma unroll
            for (int dx = -1; dx <= 1; ++dx) {
                int x   = px + dx;
                bool v  = vy & (x >= 0) & (x < WW);
                int xc  = min(max(x, 0), WW - 1);
                float val = __ldg(row + xc);
                if (v) { sum += val; cnt += 1.0f; }
            }
        }
        float avg = sum / cnt;
        float d   = avg - __ldg(runoff + idx);
        err2 = d * d;
    }

    // Deterministic block reduction: warp shuffle then shared tree.
    __shared__ float warp_sums[THREADS / 32];
    #pragma unroll
    for (int off = 16; off > 0; off >>= 1)
        err2 += __shfl_down_sync(0xFFFFFFFFu, err2, off);

    int lane = threadIdx.x & 31;
    int wid  = threadIdx.x >> 5;
    if (lane == 0) warp_sums[wid] = err2;
    __syncthreads();

    if (wid == 0) {
        float v = (lane < THREADS / 32) ? warp_sums[lane] : 0.0f;
        #pragma unroll
        for (int off = 4; off > 0; off >>= 1)
            v += __shfl_down_sync(0xFFFFFFFFu, v, off);
        if (lane == 0) g_partials[blockIdx.x] = v;
    }
}

// Deterministic finalize: fixed strided accumulation + fixed shared tree.
__global__ void __launch_bounds__(256)
finalize_kernel(float* __restrict__ out)
{
    __shared__ float sh[256];
    float v = 0.0f;
    for (int i = threadIdx.x; i < NBLK; i += 256)
        v += g_partials[i];
    sh[threadIdx.x] = v;
    __syncthreads();
    #pragma unroll
    for (int off = 128; off > 0; off >>= 1) {
        if (threadIdx.x < off) sh[threadIdx.x] += sh[threadIdx.x + off];
        __syncthreads();
    }
    if (threadIdx.x == 0)
        out[0] = sh[0] / (float)TOTAL;
}

extern "C" void kernel_launch(void* const* d_in, const int* in_sizes, int n_in,
                              void* d_out, int out_size)
{
    const float* pred   = (const float*)d_in[0];  // (B,1,H,W) f32
    const int*   pos    = (const int*)  d_in[1];  // (B,S,2)  i32
    const float* runoff = (const float*)d_in[2];  // (B,S)    f32
    float* out = (float*)d_out;

    station_loss_kernel<<<NBLK, THREADS>>>(pred, pos, runoff);
    finalize_kernel<<<1, 256>>>(out);
}